// round 6
// baseline (speedup 1.0000x reference)
#include <cuda_runtime.h>
#include <cuda_bf16.h>
#include <math.h>
#include <stdint.h>

#define D_DIM 256
#define O_DIM 32
#define NMAX 50000
#define EMAX 800000

// ---------------- scratch (static device globals; no runtime allocation) ---
__device__ float g_B[(size_t)NMAX * D_DIM];   // h1 = A@W+b
__device__ float g_C[(size_t)NMAX * D_DIM];   // nb  (fused weights)
__device__ __nv_bfloat16 g_Ah[(size_t)NMAX * D_DIM];  // GEMM input hi
__device__ __nv_bfloat16 g_Al[(size_t)NMAX * D_DIM];  // GEMM input lo
__device__ __nv_bfloat16 g_Wh[2][512 * 256];  // packed weights [n][k] hi
__device__ __nv_bfloat16 g_Wl[2][512 * 256];  // packed weights [n][k] lo
__device__ float g_biasC[2][512];
__device__ float g_Wf[2][256 * 256];          // W @ Wn per layer
__device__ float g_bf[2][256];                // b @ Wn + bn per layer
__device__ float g_dinv[NMAX];
__device__ int   g_cnt[NMAX];
__device__ int   g_rowstart[NMAX];
__device__ int   g_cursor[NMAX];
__device__ int   g_colidx[EMAX];
__device__ int   g_base;                      // global slot cursor

// ================= helpers =================================================
__device__ __forceinline__ uint32_t smem_u32(const void* p) {
    uint32_t a;
    asm("{ .reg .u64 t; cvta.to.shared.u64 t, %1; cvt.u32.u64 %0, t; }"
        : "=r"(a) : "l"(p));
    return a;
}
__device__ __forceinline__ void ldsm_x4(uint32_t* r, uint32_t addr) {
    asm volatile("ldmatrix.sync.aligned.m8n8.x4.shared.b16 {%0,%1,%2,%3}, [%4];"
                 : "=r"(r[0]), "=r"(r[1]), "=r"(r[2]), "=r"(r[3]) : "r"(addr));
}
__device__ __forceinline__ void mma_bf16(float* c, const uint32_t* a,
                                         uint32_t b0, uint32_t b1) {
    asm volatile(
        "mma.sync.aligned.m16n8k16.row.col.f32.bf16.bf16.f32 "
        "{%0,%1,%2,%3}, {%4,%5,%6,%7}, {%8,%9}, {%0,%1,%2,%3};"
        : "+f"(c[0]), "+f"(c[1]), "+f"(c[2]), "+f"(c[3])
        : "r"(a[0]), "r"(a[1]), "r"(a[2]), "r"(a[3]), "r"(b0), "r"(b1));
}
__device__ __forceinline__ void cp16(uint32_t s, const void* g, bool p) {
    asm volatile("cp.async.cg.shared.global [%0], [%1], 16, %2;"
                 :: "r"(s), "l"(g), "r"(p ? 16 : 0));
}
#define CP_COMMIT() asm volatile("cp.async.commit_group;" ::: "memory")
#define CP_WAIT(n)  asm volatile("cp.async.wait_group %0;" :: "n"(n) : "memory")
#define SW128(off) ((off) ^ (((off) >> 3) & 0x70))

// ---------------- CSR build (scan-free) ------------------------------------
__global__ void zero_csr_kernel(int n) {
    int i = blockIdx.x * blockDim.x + threadIdx.x;
    if (i < n) g_cnt[i] = 0;
    if (i == 0) g_base = 0;
}
__global__ void count_edges_kernel(const int* __restrict__ row, int e) {
    int i = blockIdx.x * blockDim.x + threadIdx.x;
    if (i < e) atomicAdd(&g_cnt[row[i]], 1);
}
__global__ void offsets_kernel(int n) {
    int i = blockIdx.x * blockDim.x + threadIdx.x;
    int lane = threadIdx.x & 31;
    int c = (i < n) ? g_cnt[i] : 0;
    int incl = c;
    #pragma unroll
    for (int o = 1; o < 32; o <<= 1) {
        int v = __shfl_up_sync(0xffffffffu, incl, o);
        if (lane >= o) incl += v;
    }
    int total = __shfl_sync(0xffffffffu, incl, 31);
    int base = 0;
    if (lane == 31 && total > 0) base = atomicAdd(&g_base, total);
    base = __shfl_sync(0xffffffffu, base, 31);
    if (i < n) {
        int start = base + incl - c;
        g_rowstart[i] = start;
        g_cursor[i]   = start;
        g_dinv[i]     = rsqrtf((float)(c + 1));
    }
}
__global__ void fill_csr_kernel(const int* __restrict__ row,
                                const int* __restrict__ col, int e) {
    int i = blockIdx.x * blockDim.x + threadIdx.x;
    if (i < e) {
        int p = atomicAdd(&g_cursor[row[i]], 1);
        g_colidx[p] = col[i];
    }
}

// ---------------- weight prep ---------------------------------------------
// blocks 0..255: Wf[k][n] = sum_j W[k][j]*Wn[j][n]; block 256: bf[n]
__global__ void fuse_wb_kernel(const float* __restrict__ W,
                               const float* __restrict__ Wn,
                               const float* __restrict__ b,
                               const float* __restrict__ bn, int layer) {
    int n = threadIdx.x;
    int kb = blockIdx.x;
    if (kb < 256) {
        const float* wrow = W + kb * 256;
        float acc = 0.0f;
        #pragma unroll 8
        for (int j = 0; j < 256; j++)
            acc = fmaf(__ldg(wrow + j), Wn[j * 256 + n], acc);
        g_Wf[layer][kb * 256 + n] = acc;
    } else {
        float acc = bn[n];
        #pragma unroll 8
        for (int j = 0; j < 256; j++)
            acc = fmaf(__ldg(b + j), Wn[j * 256 + n], acc);
        g_bf[layer][n] = acc;
    }
}
// transpose-pack Wcomb[512n][256k] hi/lo via smem tiles; also bias vec
__global__ void pack_w_kernel(const float* __restrict__ W,
                              const float* __restrict__ b, int layer) {
    __shared__ float s[32][33];
    int k0 = blockIdx.x * 32, n0 = blockIdx.y * 32;
    int tx = threadIdx.x, ty = threadIdx.y;
    #pragma unroll
    for (int i = 0; i < 4; i++) {
        int k = k0 + ty + i * 8;
        float v = (n0 < 256) ? W[k * 256 + n0 + tx]
                             : g_Wf[layer][k * 256 + (n0 - 256) + tx];
        s[ty + i * 8][tx] = v;
    }
    __syncthreads();
    #pragma unroll
    for (int i = 0; i < 4; i++) {
        int n = n0 + ty + i * 8;
        float w = s[tx][ty + i * 8];
        __nv_bfloat16 hi = __float2bfloat16(w);
        g_Wh[layer][n * 256 + k0 + tx] = hi;
        g_Wl[layer][n * 256 + k0 + tx] = __float2bfloat16(w - __bfloat162float(hi));
    }
    if (blockIdx.x == 0 && tx == 0) {
        #pragma unroll
        for (int i = 0; i < 4; i++) {
            int n = n0 + ty + i * 8;
            g_biasC[layer][n] = (n < 256) ? b[n] : g_bf[layer][n - 256];
        }
    }
}
__global__ void split_kernel(const float* __restrict__ x, int total4) {
    int i = blockIdx.x * blockDim.x + threadIdx.x;
    if (i < total4) {
        float4 v = reinterpret_cast<const float4*>(x)[i];
        __nv_bfloat16 h0 = __float2bfloat16(v.x), h1 = __float2bfloat16(v.y);
        __nv_bfloat16 h2 = __float2bfloat16(v.z), h3 = __float2bfloat16(v.w);
        __nv_bfloat162 hA, hB, lA, lB;
        hA.x = h0; hA.y = h1; hB.x = h2; hB.y = h3;
        lA.x = __float2bfloat16(v.x - __bfloat162float(h0));
        lA.y = __float2bfloat16(v.y - __bfloat162float(h1));
        lB.x = __float2bfloat16(v.z - __bfloat162float(h2));
        lB.y = __float2bfloat16(v.w - __bfloat162float(h3));
        reinterpret_cast<__nv_bfloat162*>(g_Ah)[i * 2]     = hA;
        reinterpret_cast<__nv_bfloat162*>(g_Ah)[i * 2 + 1] = hB;
        reinterpret_cast<__nv_bfloat162*>(g_Al)[i * 2]     = lA;
        reinterpret_cast<__nv_bfloat162*>(g_Al)[i * 2 + 1] = lB;
    }
}

// ---------------- HMMA GEMM: [B|C] = A @ Wcomb, split-bf16 x3 --------------
// NOTE: epilogue writes B (cols<256) or C (cols>=256) only; no dinv use, so
// this kernel has NO dependency on the CSR/dinv chain.
#define STAGE_BYTES 65536
__global__ __launch_bounds__(256)
void hmma_gemm_kernel(const __nv_bfloat16* __restrict__ Ah,
                      const __nv_bfloat16* __restrict__ Al,
                      const __nv_bfloat16* __restrict__ Wh,
                      const __nv_bfloat16* __restrict__ Wl,
                      const float* __restrict__ bias,
                      float* __restrict__ Bout, float* __restrict__ Cout,
                      int M)
{
    extern __shared__ char dsm_raw[];
    uint32_t dynu = smem_u32(dsm_raw);
    uint32_t pad = ((dynu + 127) & ~127u) - dynu;
    uint32_t sb = dynu + pad;
    const uint32_t OFF_AH = 0, OFF_AL = 16384, OFF_BH = 32768, OFF_BL = 49152;

    int tid  = threadIdx.x;
    int warp = tid >> 5, lane = tid & 31;
    int brow = blockIdx.x * 128;
    int ncb  = blockIdx.y * 128;
    int wm   = (warp >> 2) * 64;
    int wn   = (warp & 3) * 32;

    int lr  = tid >> 3;
    int lc8 = tid & 7;

    float acc[4][4][4];
    #pragma unroll
    for (int mi = 0; mi < 4; mi++)
        #pragma unroll
        for (int ni = 0; ni < 4; ni++)
            #pragma unroll
            for (int q = 0; q < 4; q++) acc[mi][ni][q] = 0.0f;

    auto load_chunk = [&](int chunk, int stage) {
        int k0 = chunk * 64;
        uint32_t sbase = sb + stage * STAGE_BYTES;
        #pragma unroll
        for (int l = 0; l < 4; l++) {
            int r = lr + l * 32;
            int gr = brow + r;
            bool p = gr < M;
            uint32_t sw = SW128((uint32_t)(r * 128 + lc8 * 16));
            size_t oa = (size_t)(p ? gr : 0) * 256 + k0 + lc8 * 8;
            cp16(sbase + OFF_AH + sw, Ah + oa, p);
            cp16(sbase + OFF_AL + sw, Al + oa, p);
            size_t ow = (size_t)(ncb + r) * 256 + k0 + lc8 * 8;
            cp16(sbase + OFF_BH + sw, Wh + ow, true);
            cp16(sbase + OFF_BL + sw, Wl + ow, true);
        }
        CP_COMMIT();
    };

    load_chunk(0, 0);

    for (int chunk = 0; chunk < 4; chunk++) {
        int stage = chunk & 1;
        if (chunk < 3) { load_chunk(chunk + 1, stage ^ 1); CP_WAIT(1); }
        else           { CP_WAIT(0); }
        __syncthreads();

        uint32_t sbase = sb + stage * STAGE_BYTES;
        #pragma unroll
        for (int ks = 0; ks < 4; ks++) {
            uint32_t kb   = (uint32_t)(ks * 32 + ((lane >> 4) & 1) * 16);
            uint32_t kswz = kb ^ ((uint32_t)(lane & 7) << 4);
            uint32_t rsub = (uint32_t)((lane & 7) + ((lane >> 3) & 1) * 8);

            uint32_t adA = sbase + (wm + rsub) * 128 + kswz;
            uint32_t adB = sbase + (wn + rsub) * 128 + kswz;

            uint32_t a[4][4];
            uint32_t bh[2][4], bl[2][4];
            #pragma unroll
            for (int mi = 0; mi < 4; mi++)
                ldsm_x4(a[mi], adA + OFF_AH + mi * 2048);
            #pragma unroll
            for (int nj = 0; nj < 2; nj++) {
                ldsm_x4(bh[nj], adB + OFF_BH + nj * 2048);
                ldsm_x4(bl[nj], adB + OFF_BL + nj * 2048);
            }
            #pragma unroll
            for (int mi = 0; mi < 4; mi++)
                #pragma unroll
                for (int ni = 0; ni < 4; ni++) {
                    int nj = ni >> 1, sel = ni & 1;
                    mma_bf16(acc[mi][ni], a[mi], bh[nj][sel], bh[nj][sel + 2]);
                    mma_bf16(acc[mi][ni], a[mi], bl[nj][sel], bl[nj][sel + 2]);
                }
            #pragma unroll
            for (int mi = 0; mi < 4; mi++)
                ldsm_x4(a[mi], adA + OFF_AL + mi * 2048);
            #pragma unroll
            for (int mi = 0; mi < 4; mi++)
                #pragma unroll
                for (int ni = 0; ni < 4; ni++) {
                    int nj = ni >> 1, sel = ni & 1;
                    mma_bf16(acc[mi][ni], a[mi], bh[nj][sel], bh[nj][sel + 2]);
                }
        }
        __syncthreads();
    }

    bool chalf = (ncb >= 256);
    int  cbase = chalf ? (ncb - 256) : ncb;
    float* Out = chalf ? Cout : Bout;
    #pragma unroll
    for (int mi = 0; mi < 4; mi++) {
        int row0 = brow + wm + mi * 16 + (lane >> 2);
        int row1 = row0 + 8;
        #pragma unroll
        for (int ni = 0; ni < 4; ni++) {
            int gcol = cbase + wn + ni * 8 + (lane & 3) * 2;
            float2 bb = *(const float2*)(bias + (chalf ? 256 : 0) + gcol);
            float2 v0, v1;
            v0.x = acc[mi][ni][0] + bb.x; v0.y = acc[mi][ni][1] + bb.y;
            v1.x = acc[mi][ni][2] + bb.x; v1.y = acc[mi][ni][3] + bb.y;
            if (row0 < M) *(float2*)(Out + (size_t)row0 * 256 + gcol) = v0;
            if (row1 < M) *(float2*)(Out + (size_t)row1 * 256 + gcol) = v1;
        }
    }
}

// ---------------- fused aggregate + mix + l2norm + relu --------------------
// gathers dinv[col]*C[col] (dinv staged in smem with the column tile).
// FINAL=0: emit bf16 hi/lo for next GEMM. FINAL=1: fuse out = h@W2 + b2.
template <int FINAL>
__global__ __launch_bounds__(256)
void agg_combine_kernel(const float* __restrict__ Bm, const float* __restrict__ C,
                        const float* __restrict__ W2,
                        const float* __restrict__ b2,
                        float* __restrict__ Out, int M)
{
    int i = blockIdx.x;
    int t = threadIdx.x;
    if (i >= M) return;

    __shared__ int cols[256];
    __shared__ float sdi[256];
    __shared__ float wsum[8];
    __shared__ float s_h[256];

    int s = g_rowstart[i];
    int e = s + g_cnt[i];
    float a0 = 0.f, a1 = 0.f, a2 = 0.f, a3 = 0.f;
    float a4 = 0.f, a5 = 0.f, a6 = 0.f, a7 = 0.f;
    for (int base = s; base < e; base += 256) {
        int m = min(256, e - base);
        if (t < m) {
            int c = g_colidx[base + t];
            cols[t] = c;
            sdi[t] = g_dinv[c];
        }
        __syncthreads();
        int j = 0;
        for (; j + 8 <= m; j += 8) {
            a0 = fmaf(sdi[j],     C[(size_t)cols[j]     * D_DIM + t], a0);
            a1 = fmaf(sdi[j + 1], C[(size_t)cols[j + 1] * D_DIM + t], a1);
            a2 = fmaf(sdi[j + 2], C[(size_t)cols[j + 2] * D_DIM + t], a2);
            a3 = fmaf(sdi[j + 3], C[(size_t)cols[j + 3] * D_DIM + t], a3);
            a4 = fmaf(sdi[j + 4], C[(size_t)cols[j + 4] * D_DIM + t], a4);
            a5 = fmaf(sdi[j + 5], C[(size_t)cols[j + 5] * D_DIM + t], a5);
            a6 = fmaf(sdi[j + 6], C[(size_t)cols[j + 6] * D_DIM + t], a6);
            a7 = fmaf(sdi[j + 7], C[(size_t)cols[j + 7] * D_DIM + t], a7);
        }
        for (; j < m; j++)
            a0 = fmaf(sdi[j], C[(size_t)cols[j] * D_DIM + t], a0);
        __syncthreads();
    }
    float acc = ((a0 + a1) + (a2 + a3)) + ((a4 + a5) + (a6 + a7));

    float di = g_dinv[i];
    float nb = C[(size_t)i * D_DIM + t];
    float prop = di * acc + di * di * nb;
    float h = Bm[(size_t)i * D_DIM + t] + 0.5f * prop + 0.5f * nb;

    float v = h * h;
    #pragma unroll
    for (int o = 16; o > 0; o >>= 1)
        v += __shfl_xor_sync(0xffffffffu, v, o);
    if ((t & 31) == 0) wsum[t >> 5] = v;
    __syncthreads();
    float tot = 0.0f;
    #pragma unroll
    for (int w = 0; w < 8; w++) tot += wsum[w];
    float nrm = sqrtf(tot);
    h = fmaxf(h / fmaxf(nrm, 1e-12f), 0.0f);

    if (FINAL == 0) {
        __nv_bfloat16 hi = __float2bfloat16(h);
        size_t off = (size_t)i * D_DIM + t;
        g_Ah[off] = hi;
        g_Al[off] = __float2bfloat16(h - __bfloat162float(hi));
    } else {
        // out[i, :] = h @ W2 + b2 ; W2 is [256][32]
        s_h[t] = h;
        __syncthreads();
        int wrp = t >> 5, lane = t & 31;
        int o = wrp * 4 + (lane >> 3);
        int jj = lane & 7;
        float oacc = 0.0f;
        #pragma unroll 8
        for (int j = jj; j < 256; j += 8)
            oacc = fmaf(s_h[j], __ldg(W2 + j * 32 + o), oacc);
        oacc += __shfl_xor_sync(0xffffffffu, oacc, 1);
        oacc += __shfl_xor_sync(0xffffffffu, oacc, 2);
        oacc += __shfl_xor_sync(0xffffffffu, oacc, 4);
        if (jj == 0)
            Out[(size_t)i * O_DIM + o] = oacc + __ldg(b2 + o);
    }
}

// ---------------- host launcher -------------------------------------------
extern "C" void kernel_launch(void* const* d_in, const int* in_sizes, int n_in,
                              void* d_out, int out_size)
{
    const float* x   = (const float*)d_in[0];
    const int*   ei  = (const int*)  d_in[1];
    const float* W0  = (const float*)d_in[2];
    const float* b0  = (const float*)d_in[3];
    const float* Wn0 = (const float*)d_in[4];
    const float* bn0 = (const float*)d_in[5];
    const float* W1  = (const float*)d_in[6];
    const float* b1  = (const float*)d_in[7];
    const float* Wn1 = (const float*)d_in[8];
    const float* bn1 = (const float*)d_in[9];
    const float* W2  = (const float*)d_in[10];
    const float* b2  = (const float*)d_in[11];

    int M = in_sizes[0] / D_DIM;
    int E = in_sizes[1] / 2;
    const int* erow = ei;
    const int* ecol = ei + E;

    float *pB, *pC, *pBiasC;
    __nv_bfloat16 *pAh, *pAl, *pWh, *pWl;
    cudaGetSymbolAddress((void**)&pB,    g_B);
    cudaGetSymbolAddress((void**)&pC,    g_C);
    cudaGetSymbolAddress((void**)&pAh,   g_Ah);
    cudaGetSymbolAddress((void**)&pAl,   g_Al);
    cudaGetSymbolAddress((void**)&pWh,   g_Wh);
    cudaGetSymbolAddress((void**)&pWl,   g_Wl);
    cudaGetSymbolAddress((void**)&pBiasC, g_biasC);

    static cudaStream_t s1 = nullptr, s2 = nullptr, s3 = nullptr;
    static cudaEvent_t evRoot, evSplit, evCsr, evPrep1;
    if (s1 == nullptr) {
        cudaStreamCreateWithFlags(&s1, cudaStreamNonBlocking);
        cudaStreamCreateWithFlags(&s2, cudaStreamNonBlocking);
        cudaStreamCreateWithFlags(&s3, cudaStreamNonBlocking);
        cudaEventCreateWithFlags(&evRoot,  cudaEventDisableTiming);
        cudaEventCreateWithFlags(&evSplit, cudaEventDisableTiming);
        cudaEventCreateWithFlags(&evCsr,   cudaEventDisableTiming);
        cudaEventCreateWithFlags(&evPrep1, cudaEventDisableTiming);
        cudaFuncSetAttribute(hmma_gemm_kernel,
                             cudaFuncAttributeMaxDynamicSharedMemorySize,
                             2 * STAGE_BYTES + 256);
    }

    int eb = (E + 255) / 256;
    int nb = (M + 255) / 256;
    dim3 gg((M + 127) / 128, 4);
    dim3 pgrid(8, 16), pblk(32, 8);

    // fork side streams off the capture-origin stream
    cudaEventRecord(evRoot, 0);
    cudaStreamWaitEvent(s1, evRoot, 0);
    cudaStreamWaitEvent(s2, evRoot, 0);
    cudaStreamWaitEvent(s3, evRoot, 0);

    // main: layer-0 weight prep
    fuse_wb_kernel<<<257, 256>>>(W0, Wn0, b0, bn0, 0);
    pack_w_kernel<<<pgrid, pblk>>>(W0, b0, 0);

    // s3: split input
    split_kernel<<<(M * D_DIM / 4 + 255) / 256, 256, 0, s3>>>(x, M * D_DIM / 4);
    cudaEventRecord(evSplit, s3);
    cudaStreamWaitEvent(0, evSplit, 0);

    // main: GEMM layer 1 (independent of CSR/dinv now)
    hmma_gemm_kernel<<<gg, 256, 2 * STAGE_BYTES + 256>>>(
        pAh, pAl, pWh, pWl, pBiasC, pB, pC, M);

    // s2: CSR build + dinv (overlaps GEMM1)
    zero_csr_kernel<<<nb, 256, 0, s2>>>(M);
    count_edges_kernel<<<eb, 256, 0, s2>>>(erow, E);
    offsets_kernel<<<nb, 256, 0, s2>>>(M);
    fill_csr_kernel<<<eb, 256, 0, s2>>>(erow, ecol, E);
    cudaEventRecord(evCsr, s2);

    // s1: layer-1 weight prep (overlaps GEMM1)
    fuse_wb_kernel<<<257, 256, 0, s1>>>(W1, Wn1, b1, bn1, 1);
    pack_w_kernel<<<pgrid, pblk, 0, s1>>>(W1, b1, 1);
    cudaEventRecord(evPrep1, s1);

    // main: aggregate layer 1 (needs CSR + dinv)
    cudaStreamWaitEvent(0, evCsr, 0);
    agg_combine_kernel<0><<<M, 256>>>(pB, pC, nullptr, nullptr, nullptr, M);

    // main: GEMM layer 2 + fused final layer
    cudaStreamWaitEvent(0, evPrep1, 0);
    hmma_gemm_kernel<<<gg, 256, 2 * STAGE_BYTES + 256>>>(
        pAh, pAl, pWh + 512 * 256, pWl + 512 * 256, pBiasC + 512, pB, pC, M);
    agg_combine_kernel<1><<<M, 256>>>(pB, pC, W2, b2, (float*)d_out, M);
}

// round 7
// speedup vs baseline: 1.4859x; 1.4859x over previous
#include <cuda_runtime.h>
#include <cuda_bf16.h>
#include <math.h>
#include <stdint.h>

#define D_DIM 256
#define O_DIM 32
#define NMAX 50000
#define EMAX 800000

// ---------------- scratch (static device globals; no runtime allocation) ---
__device__ float g_B[(size_t)NMAX * D_DIM];   // h1 = A@W+b
__device__ float g_C[(size_t)NMAX * D_DIM];   // nb  (fused weights)
__device__ __nv_bfloat16 g_Ah[(size_t)NMAX * D_DIM];  // GEMM input hi
__device__ __nv_bfloat16 g_Al[(size_t)NMAX * D_DIM];  // GEMM input lo
__device__ __nv_bfloat16 g_Wh[2][512 * 256];  // packed weights [n][k] hi
__device__ __nv_bfloat16 g_Wl[2][512 * 256];  // packed weights [n][k] lo
__device__ float g_biasC[2][512];
__device__ float g_Wf[2][256 * 256];          // W @ Wn per layer
__device__ float g_bf[2][256];                // b @ Wn + bn per layer
__device__ float g_dinv[NMAX];
__device__ int   g_cnt[NMAX];
__device__ int   g_rowstart[NMAX];
__device__ int   g_cursor[NMAX];
__device__ int   g_colidx[EMAX];
__device__ int   g_base;                      // global slot cursor

// ================= helpers =================================================
__device__ __forceinline__ uint32_t smem_u32(const void* p) {
    uint32_t a;
    asm("{ .reg .u64 t; cvta.to.shared.u64 t, %1; cvt.u32.u64 %0, t; }"
        : "=r"(a) : "l"(p));
    return a;
}
__device__ __forceinline__ void ldsm_x4(uint32_t* r, uint32_t addr) {
    asm volatile("ldmatrix.sync.aligned.m8n8.x4.shared.b16 {%0,%1,%2,%3}, [%4];"
                 : "=r"(r[0]), "=r"(r[1]), "=r"(r[2]), "=r"(r[3]) : "r"(addr));
}
__device__ __forceinline__ void mma_bf16(float* c, const uint32_t* a,
                                         uint32_t b0, uint32_t b1) {
    asm volatile(
        "mma.sync.aligned.m16n8k16.row.col.f32.bf16.bf16.f32 "
        "{%0,%1,%2,%3}, {%4,%5,%6,%7}, {%8,%9}, {%0,%1,%2,%3};"
        : "+f"(c[0]), "+f"(c[1]), "+f"(c[2]), "+f"(c[3])
        : "r"(a[0]), "r"(a[1]), "r"(a[2]), "r"(a[3]), "r"(b0), "r"(b1));
}
__device__ __forceinline__ void cp16(uint32_t s, const void* g, bool p) {
    asm volatile("cp.async.cg.shared.global [%0], [%1], 16, %2;"
                 :: "r"(s), "l"(g), "r"(p ? 16 : 0));
}
#define CP_COMMIT() asm volatile("cp.async.commit_group;" ::: "memory")
#define CP_WAIT(n)  asm volatile("cp.async.wait_group %0;" :: "n"(n) : "memory")
#define SW128(off) ((off) ^ (((off) >> 3) & 0x70))

// ---------------- CSR build (scan-free) ------------------------------------
__global__ void zero_csr_kernel(int n) {
    int i = blockIdx.x * blockDim.x + threadIdx.x;
    if (i < n) g_cnt[i] = 0;
    if (i == 0) g_base = 0;
}
__global__ void count_edges_kernel(const int* __restrict__ row, int e) {
    int i = blockIdx.x * blockDim.x + threadIdx.x;
    if (i < e) atomicAdd(&g_cnt[row[i]], 1);
}
__global__ void offsets_kernel(int n) {
    int i = blockIdx.x * blockDim.x + threadIdx.x;
    int lane = threadIdx.x & 31;
    int c = (i < n) ? g_cnt[i] : 0;
    int incl = c;
    #pragma unroll
    for (int o = 1; o < 32; o <<= 1) {
        int v = __shfl_up_sync(0xffffffffu, incl, o);
        if (lane >= o) incl += v;
    }
    int total = __shfl_sync(0xffffffffu, incl, 31);
    int base = 0;
    if (lane == 31 && total > 0) base = atomicAdd(&g_base, total);
    base = __shfl_sync(0xffffffffu, base, 31);
    if (i < n) {
        int start = base + incl - c;
        g_rowstart[i] = start;
        g_cursor[i]   = start;
        g_dinv[i]     = rsqrtf((float)(c + 1));
    }
}
__global__ void fill_csr_kernel(const int* __restrict__ row,
                                const int* __restrict__ col, int e) {
    int i = blockIdx.x * blockDim.x + threadIdx.x;
    if (i < e) {
        int p = atomicAdd(&g_cursor[row[i]], 1);
        g_colidx[p] = col[i];
    }
}

// ---------------- weight prep ---------------------------------------------
__global__ void fuse_wb_kernel(const float* __restrict__ W,
                               const float* __restrict__ Wn,
                               const float* __restrict__ b,
                               const float* __restrict__ bn, int layer) {
    int n = threadIdx.x;
    int kb = blockIdx.x;
    if (kb < 256) {
        const float* wrow = W + kb * 256;
        float acc = 0.0f;
        #pragma unroll 8
        for (int j = 0; j < 256; j++)
            acc = fmaf(__ldg(wrow + j), Wn[j * 256 + n], acc);
        g_Wf[layer][kb * 256 + n] = acc;
    } else {
        float acc = bn[n];
        #pragma unroll 8
        for (int j = 0; j < 256; j++)
            acc = fmaf(__ldg(b + j), Wn[j * 256 + n], acc);
        g_bf[layer][n] = acc;
    }
}
__global__ void pack_w_kernel(const float* __restrict__ W,
                              const float* __restrict__ b, int layer) {
    __shared__ float s[32][33];
    int k0 = blockIdx.x * 32, n0 = blockIdx.y * 32;
    int tx = threadIdx.x, ty = threadIdx.y;
    #pragma unroll
    for (int i = 0; i < 4; i++) {
        int k = k0 + ty + i * 8;
        float v = (n0 < 256) ? W[k * 256 + n0 + tx]
                             : g_Wf[layer][k * 256 + (n0 - 256) + tx];
        s[ty + i * 8][tx] = v;
    }
    __syncthreads();
    #pragma unroll
    for (int i = 0; i < 4; i++) {
        int n = n0 + ty + i * 8;
        float w = s[tx][ty + i * 8];
        __nv_bfloat16 hi = __float2bfloat16(w);
        g_Wh[layer][n * 256 + k0 + tx] = hi;
        g_Wl[layer][n * 256 + k0 + tx] = __float2bfloat16(w - __bfloat162float(hi));
    }
    if (blockIdx.x == 0 && tx == 0) {
        #pragma unroll
        for (int i = 0; i < 4; i++) {
            int n = n0 + ty + i * 8;
            g_biasC[layer][n] = (n < 256) ? b[n] : g_bf[layer][n - 256];
        }
    }
}
__global__ void split_kernel(const float* __restrict__ x, int total4) {
    int i = blockIdx.x * blockDim.x + threadIdx.x;
    if (i < total4) {
        float4 v = reinterpret_cast<const float4*>(x)[i];
        __nv_bfloat16 h0 = __float2bfloat16(v.x), h1 = __float2bfloat16(v.y);
        __nv_bfloat16 h2 = __float2bfloat16(v.z), h3 = __float2bfloat16(v.w);
        __nv_bfloat162 hA, hB, lA, lB;
        hA.x = h0; hA.y = h1; hB.x = h2; hB.y = h3;
        lA.x = __float2bfloat16(v.x - __bfloat162float(h0));
        lA.y = __float2bfloat16(v.y - __bfloat162float(h1));
        lB.x = __float2bfloat16(v.z - __bfloat162float(h2));
        lB.y = __float2bfloat16(v.w - __bfloat162float(h3));
        reinterpret_cast<__nv_bfloat162*>(g_Ah)[i * 2]     = hA;
        reinterpret_cast<__nv_bfloat162*>(g_Ah)[i * 2 + 1] = hB;
        reinterpret_cast<__nv_bfloat162*>(g_Al)[i * 2]     = lA;
        reinterpret_cast<__nv_bfloat162*>(g_Al)[i * 2 + 1] = lB;
    }
}

// ---------------- HMMA GEMM: [B|C] = A @ Wcomb, split-bf16 x3 --------------
// CTA tile 128x128, BK=32, hi|lo interleaved in 128B SMEM rows.
// Stage = 32KB (A 16KB + W 16KB); 2 stages = 64KB -> 2 CTAs/SM, 16 warps.
#define STAGE_BYTES 32768
#define OFF_B 16384
__global__ __launch_bounds__(256, 2)
void hmma_gemm_kernel(const __nv_bfloat16* __restrict__ Ah,
                      const __nv_bfloat16* __restrict__ Al,
                      const __nv_bfloat16* __restrict__ Wh,
                      const __nv_bfloat16* __restrict__ Wl,
                      const float* __restrict__ bias,
                      float* __restrict__ Bout, float* __restrict__ Cout,
                      int M)
{
    extern __shared__ char dsm_raw[];
    uint32_t dynu = smem_u32(dsm_raw);
    uint32_t pad = ((dynu + 127) & ~127u) - dynu;
    uint32_t sb = dynu + pad;

    int tid  = threadIdx.x;
    int warp = tid >> 5, lane = tid & 31;
    int brow = blockIdx.x * 128;
    int ncb  = blockIdx.y * 128;
    int wm   = (warp >> 2) * 64;
    int wn   = (warp & 3) * 32;

    float acc[4][4][4];
    #pragma unroll
    for (int mi = 0; mi < 4; mi++)
        #pragma unroll
        for (int ni = 0; ni < 4; ni++)
            #pragma unroll
            for (int q = 0; q < 4; q++) acc[mi][ni][q] = 0.0f;

    // row layout (128B): bytes 0-63 = hi[k0..k0+31], 64-127 = lo[k0..k0+31]
    int lr = tid >> 3;       // 0..31 (base row step per l)
    int lc = tid & 7;        // 16B chunk in row: 0-3 hi, 4-7 lo

    auto load_chunk = [&](int chunk, int stage) {
        int k0 = chunk * 32;
        uint32_t sbase = sb + stage * STAGE_BYTES;
        const __nv_bfloat16* asrc = (lc < 4) ? Ah : Al;
        const __nv_bfloat16* wsrc = (lc < 4) ? Wh : Wl;
        int kc = (lc & 3) * 8;
        #pragma unroll
        for (int l = 0; l < 4; l++) {            // A rows
            int r = lr + l * 32;
            int gr = brow + r;
            bool p = gr < M;
            uint32_t sw = SW128((uint32_t)(r * 128 + lc * 16));
            cp16(sbase + sw, asrc + (size_t)(p ? gr : 0) * 256 + k0 + kc, p);
        }
        #pragma unroll
        for (int l = 0; l < 4; l++) {            // W rows
            int r = lr + l * 32;
            uint32_t sw = SW128((uint32_t)(r * 128 + lc * 16));
            cp16(sbase + OFF_B + sw, wsrc + (size_t)(ncb + r) * 256 + k0 + kc, true);
        }
        CP_COMMIT();
    };

    load_chunk(0, 0);

    for (int chunk = 0; chunk < 8; chunk++) {
        int stage = chunk & 1;
        if (chunk < 7) { load_chunk(chunk + 1, stage ^ 1); CP_WAIT(1); }
        else           { CP_WAIT(0); }
        __syncthreads();

        uint32_t sbase = sb + stage * STAGE_BYTES;
        #pragma unroll
        for (int ks = 0; ks < 2; ks++) {
            uint32_t kb    = (uint32_t)(ks * 32 + ((lane >> 4) & 1) * 16);
            uint32_t kszh  = kb ^ ((uint32_t)(lane & 7) << 4);          // hi
            uint32_t kszl  = (kb + 64) ^ ((uint32_t)(lane & 7) << 4);   // lo
            uint32_t rsub  = (uint32_t)((lane & 7) + ((lane >> 3) & 1) * 8);

            uint32_t adA = sbase + (wm + rsub) * 128;
            uint32_t adB = sbase + OFF_B + (wn + rsub) * 128;

            uint32_t a[4][4];
            uint32_t bh[2][4], bl[2][4];
            #pragma unroll
            for (int mi = 0; mi < 4; mi++)
                ldsm_x4(a[mi], adA + mi * 2048 + kszh);
            #pragma unroll
            for (int nj = 0; nj < 2; nj++) {
                ldsm_x4(bh[nj], adB + nj * 2048 + kszh);
                ldsm_x4(bl[nj], adB + nj * 2048 + kszl);
            }
            #pragma unroll
            for (int mi = 0; mi < 4; mi++)
                #pragma unroll
                for (int ni = 0; ni < 4; ni++) {
                    int nj = ni >> 1, sel = ni & 1;
                    mma_bf16(acc[mi][ni], a[mi], bh[nj][sel], bh[nj][sel + 2]);
                    mma_bf16(acc[mi][ni], a[mi], bl[nj][sel], bl[nj][sel + 2]);
                }
            #pragma unroll
            for (int mi = 0; mi < 4; mi++)
                ldsm_x4(a[mi], adA + mi * 2048 + kszl);
            #pragma unroll
            for (int mi = 0; mi < 4; mi++)
                #pragma unroll
                for (int ni = 0; ni < 4; ni++) {
                    int nj = ni >> 1, sel = ni & 1;
                    mma_bf16(acc[mi][ni], a[mi], bh[nj][sel], bh[nj][sel + 2]);
                }
        }
        __syncthreads();
    }

    bool chalf = (ncb >= 256);
    int  cbase = chalf ? (ncb - 256) : ncb;
    float* Out = chalf ? Cout : Bout;
    #pragma unroll
    for (int mi = 0; mi < 4; mi++) {
        int row0 = brow + wm + mi * 16 + (lane >> 2);
        int row1 = row0 + 8;
        #pragma unroll
        for (int ni = 0; ni < 4; ni++) {
            int gcol = cbase + wn + ni * 8 + (lane & 3) * 2;
            float2 bb = *(const float2*)(bias + (chalf ? 256 : 0) + gcol);
            float2 v0, v1;
            v0.x = acc[mi][ni][0] + bb.x; v0.y = acc[mi][ni][1] + bb.y;
            v1.x = acc[mi][ni][2] + bb.x; v1.y = acc[mi][ni][3] + bb.y;
            if (row0 < M) *(float2*)(Out + (size_t)row0 * 256 + gcol) = v0;
            if (row1 < M) *(float2*)(Out + (size_t)row1 * 256 + gcol) = v1;
        }
    }
}

// ---------------- fused aggregate + mix + l2norm + relu --------------------
template <int FINAL>
__global__ __launch_bounds__(256)
void agg_combine_kernel(const float* __restrict__ Bm, const float* __restrict__ C,
                        const float* __restrict__ W2,
                        const float* __restrict__ b2,
                        float* __restrict__ Out, int M)
{
    int i = blockIdx.x;
    int t = threadIdx.x;
    if (i >= M) return;

    __shared__ int cols[256];
    __shared__ float sdi[256];
    __shared__ float wsum[8];
    __shared__ float s_h[256];

    int s = g_rowstart[i];
    int e = s + g_cnt[i];
    float a0 = 0.f, a1 = 0.f, a2 = 0.f, a3 = 0.f;
    float a4 = 0.f, a5 = 0.f, a6 = 0.f, a7 = 0.f;
    for (int base = s; base < e; base += 256) {
        int m = min(256, e - base);
        if (t < m) {
            int c = g_colidx[base + t];
            cols[t] = c;
            sdi[t] = g_dinv[c];
        }
        __syncthreads();
        int j = 0;
        for (; j + 8 <= m; j += 8) {
            a0 = fmaf(sdi[j],     C[(size_t)cols[j]     * D_DIM + t], a0);
            a1 = fmaf(sdi[j + 1], C[(size_t)cols[j + 1] * D_DIM + t], a1);
            a2 = fmaf(sdi[j + 2], C[(size_t)cols[j + 2] * D_DIM + t], a2);
            a3 = fmaf(sdi[j + 3], C[(size_t)cols[j + 3] * D_DIM + t], a3);
            a4 = fmaf(sdi[j + 4], C[(size_t)cols[j + 4] * D_DIM + t], a4);
            a5 = fmaf(sdi[j + 5], C[(size_t)cols[j + 5] * D_DIM + t], a5);
            a6 = fmaf(sdi[j + 6], C[(size_t)cols[j + 6] * D_DIM + t], a6);
            a7 = fmaf(sdi[j + 7], C[(size_t)cols[j + 7] * D_DIM + t], a7);
        }
        for (; j < m; j++)
            a0 = fmaf(sdi[j], C[(size_t)cols[j] * D_DIM + t], a0);
        __syncthreads();
    }
    float acc = ((a0 + a1) + (a2 + a3)) + ((a4 + a5) + (a6 + a7));

    float di = g_dinv[i];
    float nb = C[(size_t)i * D_DIM + t];
    float prop = di * acc + di * di * nb;
    float h = Bm[(size_t)i * D_DIM + t] + 0.5f * prop + 0.5f * nb;

    float v = h * h;
    #pragma unroll
    for (int o = 16; o > 0; o >>= 1)
        v += __shfl_xor_sync(0xffffffffu, v, o);
    if ((t & 31) == 0) wsum[t >> 5] = v;
    __syncthreads();
    float tot = 0.0f;
    #pragma unroll
    for (int w = 0; w < 8; w++) tot += wsum[w];
    float nrm = sqrtf(tot);
    h = fmaxf(h / fmaxf(nrm, 1e-12f), 0.0f);

    if (FINAL == 0) {
        __nv_bfloat16 hi = __float2bfloat16(h);
        size_t off = (size_t)i * D_DIM + t;
        g_Ah[off] = hi;
        g_Al[off] = __float2bfloat16(h - __bfloat162float(hi));
    } else {
        s_h[t] = h;
        __syncthreads();
        int wrp = t >> 5, lane = t & 31;
        int o = wrp * 4 + (lane >> 3);
        int jj = lane & 7;
        float oacc = 0.0f;
        #pragma unroll 8
        for (int j = jj; j < 256; j += 8)
            oacc = fmaf(s_h[j], __ldg(W2 + j * 32 + o), oacc);
        oacc += __shfl_xor_sync(0xffffffffu, oacc, 1);
        oacc += __shfl_xor_sync(0xffffffffu, oacc, 2);
        oacc += __shfl_xor_sync(0xffffffffu, oacc, 4);
        if (jj == 0)
            Out[(size_t)i * O_DIM + o] = oacc + __ldg(b2 + o);
    }
}

// ---------------- host launcher (single stream) ----------------------------
extern "C" void kernel_launch(void* const* d_in, const int* in_sizes, int n_in,
                              void* d_out, int out_size)
{
    const float* x   = (const float*)d_in[0];
    const int*   ei  = (const int*)  d_in[1];
    const float* W0  = (const float*)d_in[2];
    const float* b0  = (const float*)d_in[3];
    const float* Wn0 = (const float*)d_in[4];
    const float* bn0 = (const float*)d_in[5];
    const float* W1  = (const float*)d_in[6];
    const float* b1  = (const float*)d_in[7];
    const float* Wn1 = (const float*)d_in[8];
    const float* bn1 = (const float*)d_in[9];
    const float* W2  = (const float*)d_in[10];
    const float* b2  = (const float*)d_in[11];

    int M = in_sizes[0] / D_DIM;
    int E = in_sizes[1] / 2;
    const int* erow = ei;
    const int* ecol = ei + E;

    float *pB, *pC, *pBiasC;
    __nv_bfloat16 *pAh, *pAl, *pWh, *pWl;
    cudaGetSymbolAddress((void**)&pB,    g_B);
    cudaGetSymbolAddress((void**)&pC,    g_C);
    cudaGetSymbolAddress((void**)&pAh,   g_Ah);
    cudaGetSymbolAddress((void**)&pAl,   g_Al);
    cudaGetSymbolAddress((void**)&pWh,   g_Wh);
    cudaGetSymbolAddress((void**)&pWl,   g_Wl);
    cudaGetSymbolAddress((void**)&pBiasC, g_biasC);

    static bool attr_done = false;
    if (!attr_done) {
        cudaFuncSetAttribute(hmma_gemm_kernel,
                             cudaFuncAttributeMaxDynamicSharedMemorySize,
                             2 * STAGE_BYTES + 256);
        attr_done = true;
    }

    int eb = (E + 255) / 256;
    int nb = (M + 255) / 256;
    dim3 gg((M + 127) / 128, 4);
    dim3 pgrid(8, 16), pblk(32, 8);

    // CSR build + dinv
    zero_csr_kernel<<<nb, 256>>>(M);
    count_edges_kernel<<<eb, 256>>>(erow, E);
    offsets_kernel<<<nb, 256>>>(M);
    fill_csr_kernel<<<eb, 256>>>(erow, ecol, E);

    // weight prep (both layers)
    fuse_wb_kernel<<<257, 256>>>(W0, Wn0, b0, bn0, 0);
    pack_w_kernel<<<pgrid, pblk>>>(W0, b0, 0);
    fuse_wb_kernel<<<257, 256>>>(W1, Wn1, b1, bn1, 1);
    pack_w_kernel<<<pgrid, pblk>>>(W1, b1, 1);

    // split input
    split_kernel<<<(M * D_DIM / 4 + 255) / 256, 256>>>(x, M * D_DIM / 4);

    // layer 1
    hmma_gemm_kernel<<<gg, 256, 2 * STAGE_BYTES + 256>>>(
        pAh, pAl, pWh, pWl, pBiasC, pB, pC, M);
    agg_combine_kernel<0><<<M, 256>>>(pB, pC, nullptr, nullptr, nullptr, M);

    // layer 2 + fused final layer
    hmma_gemm_kernel<<<gg, 256, 2 * STAGE_BYTES + 256>>>(
        pAh, pAl, pWh + 512 * 256, pWl + 512 * 256, pBiasC + 512, pB, pC, M);
    agg_combine_kernel<1><<<M, 256>>>(pB, pC, W2, b2, (float*)d_out, M);
}